// round 2
// baseline (speedup 1.0000x reference)
#include <cuda_runtime.h>
#include <cstdint>

#define NPTS   32768
#define DDIM   64
#define KCODES 8192
#define MT     128       // rows per CTA
#define NT     128       // codes per tile

// ---------------- device scratch (no allocation allowed) --------------------
__device__ float  g_zT[DDIM * NPTS];    // z transposed  [64][32768], 8 MB
__device__ float  g_eT[DDIM * KCODES];  // emb transposed [64][8192], 2 MB
__device__ float  g_zz[NPTS];
__device__ float  g_ee[KCODES];
__device__ int    g_idx[NPTS];
__device__ double g_loss;

// ---------------- packed f32x2 helpers --------------------------------------
#define FMA_F32X2(d, a, b) \
    asm("fma.rn.f32x2 %0, %1, %2, %0;" : "+l"(d) : "l"(a), "l"(b))
#define SPLAT2(d, x) \
    asm("mov.b64 %0, {%1, %1};" : "=l"(d) : "r"(__float_as_uint(x)))
#define UNPACK2(lo, hi, v) \
    asm("mov.b64 {%0, %1}, %2;" : "=r"(lo), "=r"(hi) : "l"(v))

// ---------------- 1) norms (+ loss reset) ------------------------------------
// zz MUST be the sequential fp32 sum over the 64 features (matches XLA reduce
// rounding closely enough that the final 64-scale quantization buckets agree).
__global__ void vq_norms(const float* __restrict__ z, const float* __restrict__ e) {
    int t = blockIdx.x * blockDim.x + threadIdx.x;
    if (t == 0) g_loss = 0.0;
    if (t < NPTS) {
        const float* p = z + (size_t)t * DDIM;
        float s = 0.f;
        for (int k = 0; k < DDIM; k++) s = __fadd_rn(s, __fmul_rn(p[k], p[k]));
        g_zz[t] = s;
    } else if (t < NPTS + KCODES) {
        const float* p = e + (size_t)(t - NPTS) * DDIM;
        float s = 0.f;
        for (int k = 0; k < DDIM; k++) s = __fadd_rn(s, __fmul_rn(p[k], p[k]));
        g_ee[t - NPTS] = s;
    }
}

// ---------------- 2) transpose [R][C] -> [C][R] ------------------------------
__global__ void vq_transpose(const float* __restrict__ in, float* __restrict__ out,
                             int R, int C) {
    __shared__ float tile[32][33];
    int x = blockIdx.x * 32 + threadIdx.x;  // col in `in`
    int y = blockIdx.y * 32 + threadIdx.y;  // row in `in`
    #pragma unroll
    for (int j = 0; j < 32; j += 8)
        if (x < C && (y + j) < R)
            tile[threadIdx.y + j][threadIdx.x] = in[(size_t)(y + j) * C + x];
    __syncthreads();
    int xo = blockIdx.y * 32 + threadIdx.x;  // row in `in` (col of out-row)
    int yo = blockIdx.x * 32 + threadIdx.y;  // col in `in` (row of out)
    #pragma unroll
    for (int j = 0; j < 32; j += 8)
        if (xo < R && (yo + j) < C)
            out[(size_t)(yo + j) * R + xo] = tile[threadIdx.x][threadIdx.y + j];
}

// ---------------- 3) main: distance GEMM + fused argmin ----------------------
// 256 threads (16x16). Thread tile = 8 rows x 8 codes, codes as 4 f32x2 pairs.
__global__ void __launch_bounds__(256, 2)
vq_main() {
    extern __shared__ float sm[];
    float* z_s  = sm;                 // [64][128]
    float* e_s  = sm + 64 * 128;      // [64][128]
    float* zz_s = sm + 2 * 64 * 128;  // [128]
    float* ee_s = zz_s + 128;         // [128]
    // reduction buffers alias e_s after the tile loop:
    float* rv = e_s;                  // [128][16]
    int*   ri = (int*)(e_s + 128 * 16);

    const int tid  = threadIdx.x;
    const int trow = tid >> 4;        // 0..15
    const int tcol = tid & 15;        // 0..15
    const int row0 = blockIdx.x * MT;

    // load z tile (k-major), conflict-free float4
    for (int i = tid; i < 64 * 32; i += 256) {
        int k = i >> 5, c4 = i & 31;
        ((float4*)z_s)[k * 32 + c4] =
            ((const float4*)(g_zT + (size_t)k * NPTS + row0))[c4];
    }
    if (tid < 128) zz_s[tid] = g_zz[row0 + tid];

    float bv[8]; int bi[8];
    #pragma unroll
    for (int r = 0; r < 8; r++) { bv[r] = 3.4e38f; bi[r] = 0; }

    for (int tile = 0; tile < KCODES / NT; tile++) {
        const int col0 = tile * NT;
        __syncthreads();
        for (int i = tid; i < 64 * 32; i += 256) {
            int k = i >> 5, c4 = i & 31;
            ((float4*)e_s)[k * 32 + c4] =
                ((const float4*)(g_eT + (size_t)k * KCODES + col0))[c4];
        }
        if (tid < 128) ee_s[tid] = g_ee[col0 + tid];
        __syncthreads();

        unsigned long long acc[8][4];
        #pragma unroll
        for (int r = 0; r < 8; r++)
            #pragma unroll
            for (int c = 0; c < 4; c++) acc[r][c] = 0ull;

        const float* zp = z_s + trow * 8;
        const float* ep = e_s + tcol * 8;
        #pragma unroll 4
        for (int k = 0; k < DDIM; k++) {
            union { float4 f; unsigned long long u[2]; } ea, eb;
            float4 za = *(const float4*)(zp + k * 128);
            float4 zb = *(const float4*)(zp + k * 128 + 4);
            ea.f = *(const float4*)(ep + k * 128);
            eb.f = *(const float4*)(ep + k * 128 + 4);
            float zr[8] = {za.x, za.y, za.z, za.w, zb.x, zb.y, zb.z, zb.w};
            #pragma unroll
            for (int r = 0; r < 8; r++) {
                unsigned long long zs;
                SPLAT2(zs, zr[r]);
                FMA_F32X2(acc[r][0], zs, ea.u[0]);
                FMA_F32X2(acc[r][1], zs, ea.u[1]);
                FMA_F32X2(acc[r][2], zs, eb.u[0]);
                FMA_F32X2(acc[r][3], zs, eb.u[1]);
            }
        }
        // epilogue: d = fl( fl(zz+ee) - 2*dot ), strict < keeps lowest index
        #pragma unroll
        for (int r = 0; r < 8; r++) {
            float zzr = zz_s[trow * 8 + r];
            #pragma unroll
            for (int cp = 0; cp < 4; cp++) {
                unsigned int ulo, uhi;
                UNPACK2(ulo, uhi, acc[r][cp]);
                float dlo = __uint_as_float(ulo), dhi = __uint_as_float(uhi);
                int j0 = col0 + tcol * 8 + cp * 2;
                float t0 = __fadd_rn(zzr, ee_s[tcol * 8 + cp * 2]);
                float t1 = __fadd_rn(zzr, ee_s[tcol * 8 + cp * 2 + 1]);
                float d0 = __fmaf_rn(-2.f, dlo, t0);
                float d1 = __fmaf_rn(-2.f, dhi, t1);
                if (d0 < bv[r]) { bv[r] = d0; bi[r] = j0; }
                if (d1 < bv[r]) { bv[r] = d1; bi[r] = j0 + 1; }
            }
        }
    }

    __syncthreads();
    #pragma unroll
    for (int r = 0; r < 8; r++) {
        rv[(trow * 8 + r) * 16 + tcol] = bv[r];
        ri[(trow * 8 + r) * 16 + tcol] = bi[r];
    }
    __syncthreads();
    if (tid < 128) {
        float best = rv[tid * 16]; int besti = ri[tid * 16];
        for (int c = 1; c < 16; c++) {
            float v = rv[tid * 16 + c]; int ix = ri[tid * 16 + c];
            if (v < best || (v == best && ix < besti)) { best = v; besti = ix; }
        }
        g_idx[row0 + tid] = besti;
    }
}

// ---------------- 4) gather zq, write indices, accumulate loss ---------------
__global__ void vq_out(const float* __restrict__ z, const float* __restrict__ emb,
                       float* __restrict__ out_zq, float* __restrict__ out_idxf) {
    int t = blockIdx.x * blockDim.x + threadIdx.x;
    int nthreads = gridDim.x * blockDim.x;
    double s = 0.0;
    for (int e = t; e < NPTS * DDIM; e += nthreads) {
        int row = e >> 6, c = e & 63;
        float zv = z[e];
        float ev = emb[(size_t)g_idx[row] * DDIM + c];
        float r  = __fadd_rn(ev, -zv);              // fl(zq - z)
        if (out_zq) out_zq[e] = __fadd_rn(zv, r);   // fl(z + fl(zq - z))
        s += (double)__fmul_rn(r, r);               // fl((zq - z)^2)
    }
    if (out_idxf && t < NPTS) out_idxf[t] = (float)g_idx[t];
    __shared__ double sd[256];
    sd[threadIdx.x] = s;
    __syncthreads();
    for (int o = 128; o > 0; o >>= 1) {
        if (threadIdx.x < o) sd[threadIdx.x] += sd[threadIdx.x + o];
        __syncthreads();
    }
    if (threadIdx.x == 0) atomicAdd(&g_loss, sd[0]);
}

__global__ void vq_loss(float* __restrict__ out_loss) {
    float m = (float)g_loss / (float)(NPTS * DDIM);
    out_loss[0] = __fadd_rn(__fmul_rn(0.25f, m), m);
}

// ---------------- launch -----------------------------------------------------
extern "C" void kernel_launch(void* const* d_in, const int* in_sizes, int n_in,
                              void* d_out, int out_size) {
    const float* z   = (const float*)d_in[0];
    const float* emb = (const float*)d_in[1];
    if (n_in >= 2 && in_sizes[0] == KCODES * DDIM && in_sizes[1] == NPTS * DDIM) {
        const float* t = z; z = emb; emb = t;  // defensive swap
    }

    float* out = (float*)d_out;
    float* out_zq = nullptr; float* out_idxf = nullptr; float* out_loss = nullptr;
    const int NZ = NPTS * DDIM;
    if (out_size >= NZ + NPTS + 1) {           // [zq | min_ind | loss]
        out_zq = out; out_idxf = out + NZ; out_loss = out + NZ + NPTS;
    } else if (out_size == NZ) {
        out_zq = out;
    } else if (out_size == NPTS) {
        out_idxf = out;
    } else if (out_size == 1) {
        out_loss = out;
    } else {                                   // unknown: best effort zq
        out_zq = out;
    }

    float* zT; float* eT;
    cudaGetSymbolAddress((void**)&zT, g_zT);
    cudaGetSymbolAddress((void**)&eT, g_eT);
    cudaFuncSetAttribute(vq_main, cudaFuncAttributeMaxDynamicSharedMemorySize,
                         (2 * 64 * 128 + 256) * (int)sizeof(float));

    vq_norms<<<(NPTS + KCODES + 255) / 256, 256>>>(z, emb);
    vq_transpose<<<dim3(DDIM / 32, NPTS / 32), dim3(32, 8)>>>(z, zT, NPTS, DDIM);
    vq_transpose<<<dim3(DDIM / 32, KCODES / 32), dim3(32, 8)>>>(emb, eT, KCODES, DDIM);
    vq_main<<<NPTS / MT, 256, (2 * 64 * 128 + 256) * sizeof(float)>>>();
    vq_out<<<256, 256>>>(z, emb, out_zq, out_idxf);
    if (out_loss) vq_loss<<<1, 1>>>(out_loss);
}